// round 1
// baseline (speedup 1.0000x reference)
#include <cuda_runtime.h>
#include <cstdint>
#include <math.h>

// Problem constants (fixed by the reference)
#define L_TOT 4096
#define HIDDEN 2560
#define NH 8
#define NKV 4
#define HD 256
#define SEQ 1024
#define NSEQ 4
#define QD (NH * HD)   // 2048
#define KD (NKV * HD)  // 1024

// Scratch (device globals; allocation-free per harness rules)
__device__ float g_Q[(size_t)L_TOT * QD];
__device__ float g_K[(size_t)L_TOT * KD];
__device__ float g_V[(size_t)L_TOT * KD];
__device__ float g_S[(size_t)NH * NSEQ * SEQ * SEQ];  // 128 MB score scratch
__device__ float g_AO[(size_t)L_TOT * QD];

// ---------------- tiled fp32 GEMM core ----------------
#define BM 128
#define BN 128
#define BK 8
#define TM 8
#define TN 8
// 256 threads per block

template <bool NT>
__device__ __forceinline__ void gemm_tile(const float* __restrict__ A, int lda,
                                          const float* __restrict__ B, int ldb,
                                          float* __restrict__ C, int ldc, int K)
{
    __shared__ float As[BK][BM];
    __shared__ float Bs[BK][BN];
    const int tid = threadIdx.x;
    const int tCol = tid % (BN / TN);  // 0..15
    const int tRow = tid / (BN / TN);  // 0..15
    const int aRow = tid >> 1;         // 0..127
    const int aCol = (tid & 1) * 4;    // 0 or 4

    float acc[TM][TN];
#pragma unroll
    for (int i = 0; i < TM; i++)
#pragma unroll
        for (int j = 0; j < TN; j++) acc[i][j] = 0.f;

    for (int k0 = 0; k0 < K; k0 += BK) {
        float4 a4 = *reinterpret_cast<const float4*>(A + (size_t)aRow * lda + k0 + aCol);
        As[aCol + 0][aRow] = a4.x;
        As[aCol + 1][aRow] = a4.y;
        As[aCol + 2][aRow] = a4.z;
        As[aCol + 3][aRow] = a4.w;
        if (NT) {
            const int bRow = tid >> 1;        // n (0..127)
            const int bCol = (tid & 1) * 4;   // k
            float4 b4 = *reinterpret_cast<const float4*>(B + (size_t)bRow * ldb + k0 + bCol);
            Bs[bCol + 0][bRow] = b4.x;
            Bs[bCol + 1][bRow] = b4.y;
            Bs[bCol + 2][bRow] = b4.z;
            Bs[bCol + 3][bRow] = b4.w;
        } else {
            const int bRow = tid >> 5;         // k (0..7)
            const int bCol = (tid & 31) * 4;   // n
            float4 b4 = *reinterpret_cast<const float4*>(B + (size_t)(k0 + bRow) * ldb + bCol);
            *reinterpret_cast<float4*>(&Bs[bRow][bCol]) = b4;
        }
        __syncthreads();
#pragma unroll
        for (int k = 0; k < BK; k++) {
            float regM[TM], regN[TN];
#pragma unroll
            for (int i = 0; i < TM; i++) regM[i] = As[k][tRow * TM + i];
#pragma unroll
            for (int j = 0; j < TN; j++) regN[j] = Bs[k][tCol * TN + j];
#pragma unroll
            for (int i = 0; i < TM; i++)
#pragma unroll
                for (int j = 0; j < TN; j++) acc[i][j] = fmaf(regM[i], regN[j], acc[i][j]);
        }
        __syncthreads();
    }
#pragma unroll
    for (int i = 0; i < TM; i++)
#pragma unroll
        for (int j = 0; j < TN; j += 4) {
            float4 v = make_float4(acc[i][j], acc[i][j + 1], acc[i][j + 2], acc[i][j + 3]);
            *reinterpret_cast<float4*>(C + (size_t)(tRow * TM + i) * ldc + tCol * TN + j) = v;
        }
}

// C[M,N] = A[M,K] @ B[K,N], all row-major, dims divisible by tile sizes.
__global__ void __launch_bounds__(256) sgemm_nn(int K, const float* __restrict__ A, int lda,
                                                const float* __restrict__ B, int ldb,
                                                float* __restrict__ C, int ldc)
{
    const float* At = A + (size_t)blockIdx.y * BM * lda;
    const float* Bt = B + (size_t)blockIdx.x * BN;
    float* Ct = C + (size_t)blockIdx.y * BM * ldc + (size_t)blockIdx.x * BN;
    gemm_tile<false>(At, lda, Bt, ldb, Ct, ldc, K);
}

// Per-(token, head) RMS norm + RoPE, in place.
__global__ void __launch_bounds__(256) norm_rope_kernel(float* __restrict__ X, int nHeads,
                                                        const float* __restrict__ w,
                                                        const float* __restrict__ cosb,
                                                        const float* __restrict__ sinb)
{
    const int l = blockIdx.x, h = blockIdx.y;
    float* x = X + (size_t)l * nHeads * HD + (size_t)h * HD;
    const int i = threadIdx.x;  // 0..255
    float v = x[i];
    __shared__ float red[256];
    __shared__ float sh[256];
    red[i] = v * v;
    __syncthreads();
    for (int s = 128; s > 0; s >>= 1) {
        if (i < s) red[i] += red[i + s];
        __syncthreads();
    }
    float r = rsqrtf(red[0] * (1.0f / HD) + 1e-6f);
    float n = v * r * (1.0f + w[i]);
    sh[i] = n;
    __syncthreads();
    float rot = (i < (HD / 2)) ? -sh[i + HD / 2] : sh[i - HD / 2];
    x[i] = n * cosb[(size_t)l * HD + i] + rot * sinb[(size_t)l * HD + i];
}

// Batched Q @ K^T per (head, seq). Skips fully causal-masked tiles.
__global__ void __launch_bounds__(256) scores_kernel()
{
    if (blockIdx.x > blockIdx.y) return;  // tile entirely above diagonal -> masked
    const int z = blockIdx.z;             // 0..31
    const int h = z >> 2;
    const int s = z & 3;
    const float* A = g_Q + (size_t)s * SEQ * QD + (size_t)h * HD + (size_t)blockIdx.y * BM * QD;
    const float* B = g_K + (size_t)s * SEQ * KD + (size_t)(h >> 1) * HD + (size_t)blockIdx.x * BN * KD;
    float* C = g_S + (size_t)z * SEQ * SEQ + (size_t)blockIdx.y * BM * SEQ + (size_t)blockIdx.x * BN;
    gemm_tile<true>(A, QD, B, KD, C, SEQ, HD);
}

// Row-wise masked softmax (scale + causal) over SEQ keys. Writes 0 for masked.
__global__ void __launch_bounds__(256) softmax_kernel()
{
    const int z = blockIdx.y;
    const int row = blockIdx.x;
    float* S = g_S + (size_t)z * SEQ * SEQ + (size_t)row * SEQ;
    const int valid = row + 1;
    const int tid = threadIdx.x;
    float vals[4];
    float mx = -INFINITY;
#pragma unroll
    for (int j = 0; j < 4; j++) {
        int c = tid + j * 256;
        float v = (c < valid) ? S[c] * 0.0625f : -INFINITY;
        vals[j] = v;
        mx = fmaxf(mx, v);
    }
    __shared__ float red[256];
    red[tid] = mx;
    __syncthreads();
    for (int s2 = 128; s2 > 0; s2 >>= 1) {
        if (tid < s2) red[tid] = fmaxf(red[tid], red[tid + s2]);
        __syncthreads();
    }
    mx = red[0];
    __syncthreads();
    float ev[4];
    float lsum = 0.f;
#pragma unroll
    for (int j = 0; j < 4; j++) {
        int c = tid + j * 256;
        ev[j] = (c < valid) ? __expf(vals[j] - mx) : 0.f;
        lsum += ev[j];
    }
    red[tid] = lsum;
    __syncthreads();
    for (int s2 = 128; s2 > 0; s2 >>= 1) {
        if (tid < s2) red[tid] += red[tid + s2];
        __syncthreads();
    }
    float inv = 1.0f / red[0];
#pragma unroll
    for (int j = 0; j < 4; j++) {
        int c = tid + j * 256;
        S[c] = ev[j] * inv;
    }
}

// Batched P @ V per (head, seq); K-loop truncated by causality.
__global__ void __launch_bounds__(256) pv_kernel()
{
    const int z = blockIdx.z;
    const int h = z >> 2;
    const int s = z & 3;
    const float* A = g_S + (size_t)z * SEQ * SEQ + (size_t)blockIdx.y * BM * SEQ;
    const float* B = g_V + (size_t)s * SEQ * KD + (size_t)(h >> 1) * HD + (size_t)blockIdx.x * BN;
    float* C = g_AO + (size_t)s * SEQ * QD + (size_t)h * HD + (size_t)blockIdx.y * BM * QD +
               (size_t)blockIdx.x * BN;
    const int Keff = (blockIdx.y + 1) * BM;  // P is zero beyond the diagonal
    gemm_tile<false>(A, SEQ, B, KD, C, QD, Keff);
}

extern "C" void kernel_launch(void* const* d_in, const int* in_sizes, int n_in,
                              void* d_out, int out_size)
{
    const float* X    = (const float*)d_in[0];  // (4096, 2560)
    const float* cosb = (const float*)d_in[1];  // (4096, 256)
    const float* sinb = (const float*)d_in[2];  // (4096, 256)
    const float* Wq   = (const float*)d_in[3];  // (2560, 2048)
    const float* Wk   = (const float*)d_in[4];  // (2560, 1024)
    const float* Wv   = (const float*)d_in[5];  // (2560, 1024)
    const float* Wo   = (const float*)d_in[6];  // (2048, 2560)
    const float* qw   = (const float*)d_in[7];  // (256,)
    const float* kw   = (const float*)d_in[8];  // (256,)
    // d_in[9] = cu_seqlens: fixed [0,1024,2048,3072,4096] by construction; layout hardcoded.
    float* out = (float*)d_out;

    float *Q, *K, *V, *AO;
    cudaGetSymbolAddress((void**)&Q, g_Q);
    cudaGetSymbolAddress((void**)&K, g_K);
    cudaGetSymbolAddress((void**)&V, g_V);
    cudaGetSymbolAddress((void**)&AO, g_AO);

    // QKV projections
    sgemm_nn<<<dim3(QD / BN, L_TOT / BM), 256>>>(HIDDEN, X, HIDDEN, Wq, QD, Q, QD);
    sgemm_nn<<<dim3(KD / BN, L_TOT / BM), 256>>>(HIDDEN, X, HIDDEN, Wk, KD, K, KD);
    sgemm_nn<<<dim3(KD / BN, L_TOT / BM), 256>>>(HIDDEN, X, HIDDEN, Wv, KD, V, KD);

    // QK-norm + RoPE (in place)
    norm_rope_kernel<<<dim3(L_TOT, NH), 256>>>(Q, NH, qw, cosb, sinb);
    norm_rope_kernel<<<dim3(L_TOT, NKV), 256>>>(K, NKV, kw, cosb, sinb);

    // Attention: scores -> softmax -> PV, batched over (head, seq)
    scores_kernel<<<dim3(SEQ / BN, SEQ / BM, NH * NSEQ), 256>>>();
    softmax_kernel<<<dim3(SEQ, NH * NSEQ), 256>>>();
    pv_kernel<<<dim3(HD / BN, SEQ / BM, NH * NSEQ), 256>>>();

    // Output projection
    sgemm_nn<<<dim3(HIDDEN / BN, L_TOT / BM), 256>>>(QD, AO, QD, Wo, HIDDEN, out, HIDDEN);
}

// round 2
// speedup vs baseline: 2.5309x; 2.5309x over previous
#include <cuda_runtime.h>
#include <cstdint>
#include <math.h>

// Problem constants (fixed by the reference)
#define L_TOT 4096
#define HIDDEN 2560
#define NH 8
#define NKV 4
#define HD 256
#define SEQ 1024
#define NSEQ 4
#define QD (NH * HD)   // 2048
#define KD (NKV * HD)  // 1024

// Scratch (device globals; allocation-free per harness rules)
__device__ float g_Q[(size_t)L_TOT * QD];
__device__ float g_K[(size_t)L_TOT * KD];
__device__ float g_V[(size_t)L_TOT * KD];
__device__ float g_S[(size_t)NH * NSEQ * SEQ * SEQ];
__device__ float g_AO[(size_t)L_TOT * QD];

// ---------------- tf32 mma.sync GEMM core ----------------
// Block tile 128x128, BK=16, 256 threads (8 warps as 4x2), warp tile 32x64.
#define ASTRIDE 20     // [m][k] layout, 16 k-floats + 4 pad (conflict-free)
#define BSTRIDE_NN 132 // [k][n] layout, 128 n-floats + 4 pad
#define BSTRIDE_NT 20  // [n][k] layout

__device__ __forceinline__ void cp16(uint32_t s, const void* g) {
    asm volatile("cp.async.cg.shared.global [%0], [%1], 16;\n" ::"r"(s), "l"(g));
}
__device__ __forceinline__ void cp_commit() { asm volatile("cp.async.commit_group;\n"); }
__device__ __forceinline__ void cp_wait0() { asm volatile("cp.async.wait_group 0;\n"); }

__device__ __forceinline__ uint32_t cvt_tf32(float x) {
    uint32_t r;
    asm("cvt.rna.tf32.f32 %0, %1;" : "=r"(r) : "f"(x));
    return r;
}

__device__ __forceinline__ void mma_tf32(float* c, const uint32_t* a, uint32_t b0, uint32_t b1) {
    asm volatile(
        "mma.sync.aligned.m16n8k8.row.col.f32.tf32.tf32.f32 "
        "{%0,%1,%2,%3}, {%4,%5,%6,%7}, {%8,%9}, {%0,%1,%2,%3};\n"
        : "+f"(c[0]), "+f"(c[1]), "+f"(c[2]), "+f"(c[3])
        : "r"(a[0]), "r"(a[1]), "r"(a[2]), "r"(a[3]), "r"(b0), "r"(b1));
}

// C[128,128] tile = A[128,K] x B, A row-major at lda. NT: B[n][k] rows at ldb.
// NN: B[k][n] rows at ldb. K % 16 == 0. Caller pre-offsets A,B,C to the tile.
template <bool NT>
__device__ __forceinline__ void mma_gemm_body(const float* __restrict__ A, int lda,
                                              const float* __restrict__ B, int ldb,
                                              float* __restrict__ C, int ldc, int K)
{
    __shared__ float As[2][128 * ASTRIDE];
    __shared__ float Bs[2][NT ? 128 * BSTRIDE_NT : 16 * BSTRIDE_NN];

    const int tid = threadIdx.x;
    const int warp = tid >> 5, lane = tid & 31;
    const int gid = lane >> 2, tig = lane & 3;
    const int wm = warp & 3, wn = warp >> 2;  // 4 x 2 warp grid

    float acc[2][8][4];
#pragma unroll
    for (int i = 0; i < 2; i++)
#pragma unroll
        for (int j = 0; j < 8; j++)
#pragma unroll
            for (int r = 0; r < 4; r++) acc[i][j][r] = 0.f;

    const uint32_t sA = (uint32_t)__cvta_generic_to_shared(&As[0][0]);
    const uint32_t sB = (uint32_t)__cvta_generic_to_shared(&Bs[0][0]);

    auto load_stage = [&](int buf, int k0) {
#pragma unroll
        for (int i = 0; i < 2; i++) {
            int chunk = tid * 2 + i;  // 0..511
            int row = chunk >> 2, cc = chunk & 3;
            cp16(sA + (uint32_t)(buf * 128 * ASTRIDE + row * ASTRIDE + cc * 4) * 4,
                 A + (size_t)row * lda + k0 + cc * 4);
        }
        if (NT) {
#pragma unroll
            for (int i = 0; i < 2; i++) {
                int chunk = tid * 2 + i;
                int row = chunk >> 2, cc = chunk & 3;
                cp16(sB + (uint32_t)(buf * 128 * BSTRIDE_NT + row * BSTRIDE_NT + cc * 4) * 4,
                     B + (size_t)row * ldb + k0 + cc * 4);
            }
        } else {
#pragma unroll
            for (int i = 0; i < 2; i++) {
                int chunk = tid * 2 + i;
                int row = chunk >> 5, cc = chunk & 31;
                cp16(sB + (uint32_t)(buf * 16 * BSTRIDE_NN + row * BSTRIDE_NN + cc * 4) * 4,
                     B + (size_t)(k0 + row) * ldb + cc * 4);
            }
        }
        cp_commit();
    };

    const int KT = K >> 4;
    load_stage(0, 0);

    for (int kt = 0; kt < KT; kt++) {
        cp_wait0();
        __syncthreads();
        const int buf = kt & 1;
        if (kt + 1 < KT) load_stage(buf ^ 1, (kt + 1) * 16);

#pragma unroll
        for (int ks = 0; ks < 16; ks += 8) {
            uint32_t af[2][4];
#pragma unroll
            for (int mt = 0; mt < 2; mt++) {
                const int mrow = wm * 32 + mt * 16 + gid;
                af[mt][0] = cvt_tf32(As[buf][mrow * ASTRIDE + ks + tig]);
                af[mt][1] = cvt_tf32(As[buf][(mrow + 8) * ASTRIDE + ks + tig]);
                af[mt][2] = cvt_tf32(As[buf][mrow * ASTRIDE + ks + tig + 4]);
                af[mt][3] = cvt_tf32(As[buf][(mrow + 8) * ASTRIDE + ks + tig + 4]);
            }
#pragma unroll
            for (int nt = 0; nt < 8; nt++) {
                const int ncol = wn * 64 + nt * 8 + gid;
                float b0f, b1f;
                if (NT) {
                    b0f = Bs[buf][ncol * BSTRIDE_NT + ks + tig];
                    b1f = Bs[buf][ncol * BSTRIDE_NT + ks + tig + 4];
                } else {
                    b0f = Bs[buf][(ks + tig) * BSTRIDE_NN + ncol];
                    b1f = Bs[buf][(ks + tig + 4) * BSTRIDE_NN + ncol];
                }
                const uint32_t b0 = cvt_tf32(b0f), b1 = cvt_tf32(b1f);
#pragma unroll
                for (int mt = 0; mt < 2; mt++) mma_tf32(acc[mt][nt], af[mt], b0, b1);
            }
        }
    }

    // Epilogue: c0,c1 at (row, 2*tig..), c2,c3 at (row+8, ..)
#pragma unroll
    for (int mt = 0; mt < 2; mt++) {
        const int mrow = wm * 32 + mt * 16 + gid;
#pragma unroll
        for (int nt = 0; nt < 8; nt++) {
            const int ncol = wn * 64 + nt * 8 + 2 * tig;
            float2 v0 = make_float2(acc[mt][nt][0], acc[mt][nt][1]);
            *reinterpret_cast<float2*>(C + (size_t)mrow * ldc + ncol) = v0;
            float2 v1 = make_float2(acc[mt][nt][2], acc[mt][nt][3]);
            *reinterpret_cast<float2*>(C + (size_t)(mrow + 8) * ldc + ncol) = v1;
        }
    }
}

__global__ void __launch_bounds__(256) gemm_nn_k(int K, const float* __restrict__ A, int lda,
                                                 const float* __restrict__ B, int ldb,
                                                 float* __restrict__ C, int ldc)
{
    A += (size_t)blockIdx.y * 128 * lda;
    B += (size_t)blockIdx.x * 128;
    C += (size_t)blockIdx.y * 128 * ldc + (size_t)blockIdx.x * 128;
    mma_gemm_body<false>(A, lda, B, ldb, C, ldc, K);
}

// Q @ K^T per (head, seq); skips fully-masked tiles.
__global__ void __launch_bounds__(256) scores_k()
{
    if ((int)blockIdx.x > (int)blockIdx.y) return;
    const int z = blockIdx.z;
    const int h = z >> 2, s = z & 3;
    const float* A = g_Q + (size_t)s * SEQ * QD + (size_t)h * HD + (size_t)blockIdx.y * 128 * QD;
    const float* B = g_K + (size_t)s * SEQ * KD + (size_t)(h >> 1) * HD + (size_t)blockIdx.x * 128 * KD;
    float* C = g_S + (size_t)z * SEQ * SEQ + (size_t)blockIdx.y * 128 * SEQ + (size_t)blockIdx.x * 128;
    mma_gemm_body<true>(A, QD, B, KD, C, SEQ, HD);
}

// P @ V per (head, seq); K-loop truncated by causality (P zero past diagonal).
__global__ void __launch_bounds__(256) pv_k()
{
    const int z = blockIdx.z;
    const int h = z >> 2, s = z & 3;
    const float* A = g_S + (size_t)z * SEQ * SEQ + (size_t)blockIdx.y * 128 * SEQ;
    const float* B = g_V + (size_t)s * SEQ * KD + (size_t)(h >> 1) * HD + (size_t)blockIdx.x * 128;
    float* C = g_AO + (size_t)s * SEQ * QD + (size_t)h * HD + (size_t)blockIdx.y * 128 * QD +
               (size_t)blockIdx.x * 128;
    mma_gemm_body<false>(A, SEQ, B, KD, C, QD, (blockIdx.y + 1) * 128);
}

// Per-(token, head) RMS norm + RoPE, in place.
__global__ void __launch_bounds__(256) norm_rope_kernel(float* __restrict__ X, int nHeads,
                                                        const float* __restrict__ w,
                                                        const float* __restrict__ cosb,
                                                        const float* __restrict__ sinb)
{
    const int l = blockIdx.x, h = blockIdx.y;
    float* x = X + (size_t)l * nHeads * HD + (size_t)h * HD;
    const int i = threadIdx.x;  // 0..255
    float v = x[i];
    __shared__ float red[256];
    __shared__ float sh[256];
    red[i] = v * v;
    __syncthreads();
    for (int s = 128; s > 0; s >>= 1) {
        if (i < s) red[i] += red[i + s];
        __syncthreads();
    }
    float r = rsqrtf(red[0] * (1.0f / HD) + 1e-6f);
    float n = v * r * (1.0f + w[i]);
    sh[i] = n;
    __syncthreads();
    float rot = (i < (HD / 2)) ? -sh[i + HD / 2] : sh[i - HD / 2];
    x[i] = n * cosb[(size_t)l * HD + i] + rot * sinb[(size_t)l * HD + i];
}

// Row-wise masked softmax (scale + causal) over SEQ keys. Writes 0 for masked.
__global__ void __launch_bounds__(256) softmax_kernel()
{
    const int z = blockIdx.y;
    const int row = blockIdx.x;
    float* S = g_S + (size_t)z * SEQ * SEQ + (size_t)row * SEQ;
    const int valid = row + 1;
    const int tid = threadIdx.x;
    float vals[4];
    float mx = -INFINITY;
#pragma unroll
    for (int j = 0; j < 4; j++) {
        int c = tid + j * 256;
        float v = (c < valid) ? S[c] * 0.0625f : -INFINITY;
        vals[j] = v;
        mx = fmaxf(mx, v);
    }
    __shared__ float red[256];
    red[tid] = mx;
    __syncthreads();
    for (int s2 = 128; s2 > 0; s2 >>= 1) {
        if (tid < s2) red[tid] = fmaxf(red[tid], red[tid + s2]);
        __syncthreads();
    }
    mx = red[0];
    __syncthreads();
    float ev[4];
    float lsum = 0.f;
#pragma unroll
    for (int j = 0; j < 4; j++) {
        int c = tid + j * 256;
        ev[j] = (c < valid) ? __expf(vals[j] - mx) : 0.f;
        lsum += ev[j];
    }
    red[tid] = lsum;
    __syncthreads();
    for (int s2 = 128; s2 > 0; s2 >>= 1) {
        if (tid < s2) red[tid] += red[tid + s2];
        __syncthreads();
    }
    float inv = 1.0f / red[0];
#pragma unroll
    for (int j = 0; j < 4; j++) {
        int c = tid + j * 256;
        S[c] = ev[j] * inv;
    }
}

extern "C" void kernel_launch(void* const* d_in, const int* in_sizes, int n_in,
                              void* d_out, int out_size)
{
    const float* X    = (const float*)d_in[0];  // (4096, 2560)
    const float* cosb = (const float*)d_in[1];  // (4096, 256)
    const float* sinb = (const float*)d_in[2];  // (4096, 256)
    const float* Wq   = (const float*)d_in[3];  // (2560, 2048)
    const float* Wk   = (const float*)d_in[4];  // (2560, 1024)
    const float* Wv   = (const float*)d_in[5];  // (2560, 1024)
    const float* Wo   = (const float*)d_in[6];  // (2048, 2560)
    const float* qw   = (const float*)d_in[7];  // (256,)
    const float* kw   = (const float*)d_in[8];  // (256,)
    // d_in[9] = cu_seqlens: fixed [0,1024,2048,3072,4096]; layout hardcoded.
    float* out = (float*)d_out;

    float *Q, *K, *V, *AO;
    cudaGetSymbolAddress((void**)&Q, g_Q);
    cudaGetSymbolAddress((void**)&K, g_K);
    cudaGetSymbolAddress((void**)&V, g_V);
    cudaGetSymbolAddress((void**)&AO, g_AO);

    // QKV projections (tf32 tensor-core GEMM)
    gemm_nn_k<<<dim3(QD / 128, L_TOT / 128), 256>>>(HIDDEN, X, HIDDEN, Wq, QD, Q, QD);
    gemm_nn_k<<<dim3(KD / 128, L_TOT / 128), 256>>>(HIDDEN, X, HIDDEN, Wk, KD, K, KD);
    gemm_nn_k<<<dim3(KD / 128, L_TOT / 128), 256>>>(HIDDEN, X, HIDDEN, Wv, KD, V, KD);

    // QK-norm + RoPE (in place)
    norm_rope_kernel<<<dim3(L_TOT, NH), 256>>>(Q, NH, qw, cosb, sinb);
    norm_rope_kernel<<<dim3(L_TOT, NKV), 256>>>(K, NKV, kw, cosb, sinb);

    // Attention: scores -> softmax -> PV
    scores_k<<<dim3(SEQ / 128, SEQ / 128, NH * NSEQ), 256>>>();
    softmax_kernel<<<dim3(SEQ, NH * NSEQ), 256>>>();
    pv_k<<<dim3(HD / 128, SEQ / 128, NH * NSEQ), 256>>>();

    // Output projection
    gemm_nn_k<<<dim3(HIDDEN / 128, L_TOT / 128), 256>>>(QD, AO, QD, Wo, HIDDEN, out, HIDDEN);
}